// round 3
// baseline (speedup 1.0000x reference)
#include <cuda_runtime.h>
#include <cuda_bf16.h>

// Conv3x3 (stride1, pad1, no bias) + fused PixelUnshuffle(2), packed f32x2 FMA.
// x: (8, 96, 256, 256) f32, W: (48, 96, 3, 3) f32
// out: (8, 192, 128, 128) f32:
//   out[b, oc*4 + (h&1)*2 + (w&1), h>>1, w>>1] = conv(x,W)[b, oc, h, w]
//
// Block: 16x32 output tile, all 48 oc. 256 thr = 2 oc-groups x 128 px slots,
// 4 px/thread held as 2 f32x2 accumulator pairs. Weights staged duplicated
// (float2 {w,w}) in smem so each tap feeds fma.rn.f32x2 directly.

#define BATCH 8
#define IC    96
#define HH    256
#define WW    256
#define OC    48
#define TH    16
#define TW    32
#define ICC   8
#define NCHUNK (IC / ICC)

#define XS_FLOATS (ICC * (TH + 2) * (TW + 4))       // 8*18*36 = 5184 -> 20736 B
#define WS_PAIRS  (OC * ICC * 10)                   // 48*8*10 pairs -> 30720 B
#define SMEM_BYTES (XS_FLOATS * 4 + WS_PAIRS * 8)   // 51456

typedef unsigned long long u64;

__device__ __forceinline__ u64 pack2(float lo, float hi) {
    u64 r;
    asm("mov.b64 %0, {%1, %2};" : "=l"(r) : "f"(lo), "f"(hi));
    return r;
}
__device__ __forceinline__ void unpack2(u64 v, float& lo, float& hi) {
    asm("mov.b64 {%0, %1}, %2;" : "=f"(lo), "=f"(hi) : "l"(v));
}
__device__ __forceinline__ void fma2(u64& d, u64 a, u64 b) {
    asm("fma.rn.f32x2 %0, %1, %2, %0;" : "+l"(d) : "l"(a), "l"(b));
}

__global__ void __launch_bounds__(256, 1)
conv3x3_unshuffle_f32x2_kernel(const float* __restrict__ x,
                               const float* __restrict__ Wg,
                               float* __restrict__ out)
{
    extern __shared__ char smem_raw[];
    float (*xs)[TH + 2][TW + 4] = (float(*)[TH + 2][TW + 4])smem_raw;
    float2 (*ws2)[ICC][10] = (float2(*)[ICC][10])(smem_raw + XS_FLOATS * 4);

    const int tid  = threadIdx.x;
    const int ocg  = tid >> 7;         // uniform per warp
    const int slot = tid & 127;
    const int pr   = slot >> 3;        // 0..15
    const int sc   = slot & 7;         // 0..7 -> px cols sc*4..sc*4+3

    const int w0 = blockIdx.x * TW;
    const int h0 = blockIdx.y * TH;
    const int b  = blockIdx.z;

    u64 acc[24][2];                    // [oc][q], q=0 -> px(0,1), q=1 -> px(2,3)
#pragma unroll
    for (int oc = 0; oc < 24; ++oc) { acc[oc][0] = 0ULL; acc[oc][1] = 0ULL; }

    const long long x_b = (long long)b * IC * HH * WW;

    for (int chunk = 0; chunk < NCHUNK; ++chunk) {
        const int ic0 = chunk * ICC;
        __syncthreads();

        // ---- stage input tile (18 x 34 per ic, zero-padded at borders) ----
        {
            const int total = ICC * (TH + 2) * (TW + 2);   // 4896
            for (int i = tid; i < total; i += 256) {
                const int ic  = i / ((TH + 2) * (TW + 2));
                const int rem = i % ((TH + 2) * (TW + 2));
                const int row = rem / (TW + 2);
                const int col = rem % (TW + 2);
                const int h = h0 - 1 + row;
                const int w = w0 - 1 + col;
                float v = 0.0f;
                if ((unsigned)h < HH && (unsigned)w < WW)
                    v = x[x_b + ((long long)(ic0 + ic) * HH + h) * WW + w];
                xs[ic][row][col] = v;
            }
        }
        // ---- stage weights, duplicated into both f32x2 lanes ----
        {
            const int total = OC * ICC * 9;                 // 3456
            for (int i = tid; i < total; i += 256) {
                const int oc  = i / (ICC * 9);
                const int rem = i % (ICC * 9);
                const int ic  = rem / 9;
                const int k   = rem % 9;
                const float v = Wg[oc * (IC * 9) + (ic0 + ic) * 9 + k];
                ws2[oc][ic][k] = make_float2(v, v);
            }
        }
        __syncthreads();

#pragma unroll 1
        for (int ic = 0; ic < ICC; ++ic) {
            // overlapping adjacent-pixel pairs per row: pair(i) = (xr[i], xr[i+1]), i=0..4
            u64 p0[5], p1[5], p2[5];
            {
                const float* base0 = &xs[ic][pr + 0][sc * 4];
                const float* base1 = &xs[ic][pr + 1][sc * 4];
                const float* base2 = &xs[ic][pr + 2][sc * 4];
                float4 a; float2 c;
                a = *(const float4*)base0; c = *(const float2*)(base0 + 4);
                p0[0]=pack2(a.x,a.y); p0[1]=pack2(a.y,a.z); p0[2]=pack2(a.z,a.w);
                p0[3]=pack2(a.w,c.x); p0[4]=pack2(c.x,c.y);
                a = *(const float4*)base1; c = *(const float2*)(base1 + 4);
                p1[0]=pack2(a.x,a.y); p1[1]=pack2(a.y,a.z); p1[2]=pack2(a.z,a.w);
                p1[3]=pack2(a.w,c.x); p1[4]=pack2(c.x,c.y);
                a = *(const float4*)base2; c = *(const float2*)(base2 + 4);
                p2[0]=pack2(a.x,a.y); p2[1]=pack2(a.y,a.z); p2[2]=pack2(a.z,a.w);
                p2[3]=pack2(a.w,c.x); p2[4]=pack2(c.x,c.y);
            }
#pragma unroll
            for (int oc = 0; oc < 24; ++oc) {
                const u64* wq = (const u64*)&ws2[ocg * 24 + oc][ic][0];
                ulonglong2 wab = *(const ulonglong2*)(wq);      // taps 0,1
                ulonglong2 wcd = *(const ulonglong2*)(wq + 2);  // taps 2,3
                ulonglong2 wef = *(const ulonglong2*)(wq + 4);  // taps 4,5
                ulonglong2 wgh = *(const ulonglong2*)(wq + 6);  // taps 6,7
                u64 w8 = wq[8];                                  // tap 8
                // row0: taps 0..2, row1: taps 3..5, row2: taps 6..8
                fma2(acc[oc][0], wab.x, p0[0]);  fma2(acc[oc][1], wab.x, p0[2]);
                fma2(acc[oc][0], wab.y, p0[1]);  fma2(acc[oc][1], wab.y, p0[3]);
                fma2(acc[oc][0], wcd.x, p0[2]);  fma2(acc[oc][1], wcd.x, p0[4]);
                fma2(acc[oc][0], wcd.y, p1[0]);  fma2(acc[oc][1], wcd.y, p1[2]);
                fma2(acc[oc][0], wef.x, p1[1]);  fma2(acc[oc][1], wef.x, p1[3]);
                fma2(acc[oc][0], wef.y, p1[2]);  fma2(acc[oc][1], wef.y, p1[4]);
                fma2(acc[oc][0], wgh.x, p2[0]);  fma2(acc[oc][1], wgh.x, p2[2]);
                fma2(acc[oc][0], wgh.y, p2[1]);  fma2(acc[oc][1], wgh.y, p2[3]);
                fma2(acc[oc][0], w8,    p2[2]);  fma2(acc[oc][1], w8,    p2[4]);
            }
        }
    }

    // ---- epilogue: fused PixelUnshuffle(2) ----
    const int h  = h0 + pr;
    const int i2 = (h & 1) * 2;
    const int h2 = h >> 1;
    const int w2base = (w0 + sc * 4) >> 1;
#pragma unroll
    for (int oc = 0; oc < 24; ++oc) {
        const int oc_g = ocg * 24 + oc;
#pragma unroll
        for (int q = 0; q < 2; ++q) {
            float lo, hi;
            unpack2(acc[oc][q], lo, hi);
            const int w2 = w2base + q;
            const long long base = (((long long)b * 192 + oc_g * 4 + i2) * 128 + h2) * 128 + w2;
            out[base]       = lo;   // px even -> (w&1)==0
            out[base + 128 * 128] = hi;  // px odd -> channel +1
        }
    }
}

extern "C" void kernel_launch(void* const* d_in, const int* in_sizes, int n_in,
                              void* d_out, int out_size)
{
    const float* x  = (const float*)d_in[0];
    const float* Wg = (const float*)d_in[1];
    float* out = (float*)d_out;

    static int configured = 0;
    if (!configured) {
        cudaFuncSetAttribute(conv3x3_unshuffle_f32x2_kernel,
                             cudaFuncAttributeMaxDynamicSharedMemorySize, SMEM_BYTES);
        configured = 1;
    }

    dim3 grid(WW / TW, HH / TH, BATCH);   // (8, 16, 8)
    conv3x3_unshuffle_f32x2_kernel<<<grid, 256, SMEM_BYTES>>>(x, Wg, out);
}

// round 6
// speedup vs baseline: 1.0037x; 1.0037x over previous
#include <cuda_runtime.h>
#include <cuda_bf16.h>
#include <cstdint>

// Conv3x3(s1,p1) + PixelUnshuffle(2) as warp-level mma.sync implicit GEMM.
// x:(8,96,256,256)f32  W:(48,96,3,3)f32  out:(8,192,128,128)f32
// Per CTA: one h-row, 128 w pixels (M=128), all 48 oc (N=48), K=96ic x 9 taps.
// fp32 -> bf16 hi+lo split; 3 passes (hh, hl, lh); fp32 accum in registers.
// Tap shifts are pixel-row shifts in ldmatrix addresses (no im2col copies).
// B fragments: weights stored [oc][ic] row-major -> NON-transposed ldmatrix
// yields b0=(k consecutive, n=l/4) directly.

#define IC  96
#define HH  256
#define WW  256
#define OCN 48

#define ICC 16
#define NCH 6

#define A_STRIDE_H 24                    // halfwords per px row: 16 used + 8 pad (48B, conflict-free)
#define A_PLANE_H  (130 * A_STRIDE_H)    // per dy row
#define A_BYTES    (3 * A_PLANE_H * 2)   // 18720
#define OFF_AHI    0
#define OFF_ALO    A_BYTES
#define OFF_WHI    (2 * A_BYTES)         // 37440
#define W_BYTES    (9 * OCN * IC * 2)    // 82944
#define OFF_WLO    (OFF_WHI + W_BYTES)
#define SMEM_BYTES (OFF_WLO + W_BYTES)   // 203328

static __device__ __forceinline__ uint32_t smem_u32(const void* p) {
    uint32_t a;
    asm("{ .reg .u64 t; cvta.to.shared.u64 t, %1; cvt.u32.u64 %0, t; }" : "=r"(a) : "l"(p));
    return a;
}
static __device__ __forceinline__ void mma_bf16(float* d, const uint32_t* a, const uint32_t* b) {
    asm volatile(
        "mma.sync.aligned.m16n8k16.row.col.f32.bf16.bf16.f32 "
        "{%0,%1,%2,%3}, {%4,%5,%6,%7}, {%8,%9}, {%0,%1,%2,%3};"
        : "+f"(d[0]), "+f"(d[1]), "+f"(d[2]), "+f"(d[3])
        : "r"(a[0]), "r"(a[1]), "r"(a[2]), "r"(a[3]), "r"(b[0]), "r"(b[1]));
}
static __device__ __forceinline__ void ldsm_x4(uint32_t* r, uint32_t addr) {
    asm volatile("ldmatrix.sync.aligned.m8n8.x4.shared.b16 {%0,%1,%2,%3}, [%4];"
                 : "=r"(r[0]), "=r"(r[1]), "=r"(r[2]), "=r"(r[3]) : "r"(addr));
}
static __device__ __forceinline__ void ldsm_x2(uint32_t* r, uint32_t addr) {
    asm volatile("ldmatrix.sync.aligned.m8n8.x2.shared.b16 {%0,%1}, [%2];"
                 : "=r"(r[0]), "=r"(r[1]) : "r"(addr));
}
static __device__ __forceinline__ void split_bf16(float v, unsigned short& h, unsigned short& l) {
    __nv_bfloat16 hb = __float2bfloat16(v);
    __nv_bfloat16 lb = __float2bfloat16(v - __bfloat162float(hb));
    h = __bfloat16_as_ushort(hb);
    l = __bfloat16_as_ushort(lb);
}

__global__ void __launch_bounds__(256, 1)
conv_unshuffle_mma(const float* __restrict__ x,
                   const float* __restrict__ Wg,
                   float* __restrict__ out)
{
    extern __shared__ __align__(128) char sm[];
    const uint32_t smb = smem_u32(sm);
    unsigned short* aHi = (unsigned short*)(sm + OFF_AHI);
    unsigned short* aLo = (unsigned short*)(sm + OFF_ALO);
    unsigned short* wHi = (unsigned short*)(sm + OFF_WHI);
    unsigned short* wLo = (unsigned short*)(sm + OFF_WLO);

    const int tid  = threadIdx.x;
    const int lane = tid & 31;
    const int wid  = tid >> 5;
    const int mbase = (wid & 3) * 32;
    const int nbase = (wid >> 2) * 24;

    const int w0 = blockIdx.x * 128;
    const int h  = blockIdx.y;
    const int b  = blockIdx.z;
    const long long x_b = (long long)b * IC * HH * WW;

    // ---- stage ALL weights once: wHi/wLo[tap][oc][ic] ----
    for (int idx = tid; idx < 9 * OCN * IC; idx += 256) {
        const int tap = idx / (OCN * IC);
        const int r   = idx - tap * (OCN * IC);
        const int oc  = r / IC;
        const int ic  = r - oc * IC;
        unsigned short hi, lo;
        split_bf16(Wg[oc * (IC * 9) + ic * 9 + tap], hi, lo);
        const int hidx = (tap * OCN + oc) * IC + ic;
        wHi[hidx] = hi;
        wLo[hidx] = lo;
    }

    float acc[2][3][4];
#pragma unroll
    for (int mt = 0; mt < 2; ++mt)
#pragma unroll
        for (int nt = 0; nt < 3; ++nt)
#pragma unroll
            for (int e = 0; e < 4; ++e) acc[mt][nt][e] = 0.0f;

    // per-lane ldmatrix bases
    const int lrow  = lane & 15;
    const int lkoff = (lane >> 4) * 16;      // byte offset for k 8..15 halves
    uint32_t aBase[2];
#pragma unroll
    for (int mt = 0; mt < 2; ++mt)
        aBase[mt] = smb + OFF_AHI + (uint32_t)((mbase + mt * 16 + lrow) * A_STRIDE_H) * 2 + lkoff;
    const uint32_t bBase  = smb + OFF_WHI + (uint32_t)((nbase + lrow) * IC) * 2 + lkoff;
    const uint32_t bBase2 = smb + OFF_WHI + (uint32_t)((nbase + 16 + (lane & 7)) * IC) * 2
                          + ((lane >> 3) & 1) * 16;

    for (int ch = 0; ch < NCH; ++ch) {
        const int ic0 = ch * ICC;
        __syncthreads();   // previous chunk's compute done before overwrite

        // ---- stage A chunk: aHi/aLo[dy][px 0..129][ic 0..15] ----
        for (int idx = tid; idx < 3 * 130 * ICC; idx += 256) {
            const int ici = idx / 390;
            const int rem = idx - ici * 390;
            const int dyy = rem / 130;
            const int px  = rem - dyy * 130;
            const int hin = h + dyy - 1;
            const int win = w0 + px - 1;
            float v = 0.0f;
            if ((unsigned)hin < HH && (unsigned)win < WW)
                v = x[x_b + (long long)(ic0 + ici) * (HH * WW) + hin * WW + win];
            unsigned short hi, lo;
            split_bf16(v, hi, lo);
            const int hidx = (dyy * 130 + px) * A_STRIDE_H + ici;
            aHi[hidx] = hi;
            aLo[hidx] = lo;
        }
        __syncthreads();

        const uint32_t icb = (uint32_t)(ic0 * 2);
#pragma unroll
        for (int tap = 0; tap < 9; ++tap) {
            const int dyy = tap / 3;
            const int dxx = tap % 3;
            const uint32_t aoff = (uint32_t)((dyy * 130 + dxx) * (A_STRIDE_H * 2));
            const uint32_t woff = (uint32_t)(tap * OCN * IC * 2) + icb;

            uint32_t ah[2][4], al[2][4];
            ldsm_x4(ah[0], aBase[0] + aoff);
            ldsm_x4(ah[1], aBase[1] + aoff);
            ldsm_x4(al[0], aBase[0] + aoff + A_BYTES);
            ldsm_x4(al[1], aBase[1] + aoff + A_BYTES);

            uint32_t bh01[4], bh2[2], bl01[4], bl2[2];
            ldsm_x4(bh01, bBase  + woff);
            ldsm_x2(bh2,  bBase2 + woff);
            ldsm_x4(bl01, bBase  + woff + W_BYTES);
            ldsm_x2(bl2,  bBase2 + woff + W_BYTES);

            uint32_t bh[3][2] = { {bh01[0], bh01[2]}, {bh01[1], bh01[3]}, {bh2[0], bh2[1]} };
            uint32_t bl[3][2] = { {bl01[0], bl01[2]}, {bl01[1], bl01[3]}, {bl2[0], bl2[1]} };

#pragma unroll
            for (int mt = 0; mt < 2; ++mt)
#pragma unroll
                for (int nt = 0; nt < 3; ++nt) {
                    mma_bf16(acc[mt][nt], ah[mt], bh[nt]);
                    mma_bf16(acc[mt][nt], ah[mt], bl[nt]);
                    mma_bf16(acc[mt][nt], al[mt], bh[nt]);
                }
        }
    }

    // ---- epilogue: fused PixelUnshuffle(2) scatter ----
    const int qrow = lane >> 2;          // 0..7
    const int c2   = (lane & 3) * 2;
    const int h2   = h >> 1;
    const int i2   = (h & 1) * 2;
#pragma unroll
    for (int mt = 0; mt < 2; ++mt) {
#pragma unroll
        for (int pair = 0; pair < 2; ++pair) {
            const int m  = mbase + mt * 16 + qrow + pair * 8;
            const int w  = w0 + m;
            const int cb = i2 + (w & 1);
            const int w2 = w >> 1;
            const long long pxbase = (((long long)b * 192 + cb) * 128 + h2) * 128 + w2;
#pragma unroll
            for (int nt = 0; nt < 3; ++nt) {
                const int oc0 = nbase + nt * 8 + c2;
                out[pxbase + (long long)(oc0    ) * 4 * 128 * 128] = acc[mt][nt][pair * 2 + 0];
                out[pxbase + (long long)(oc0 + 1) * 4 * 128 * 128] = acc[mt][nt][pair * 2 + 1];
            }
        }
    }
}

extern "C" void kernel_launch(void* const* d_in, const int* in_sizes, int n_in,
                              void* d_out, int out_size)
{
    const float* x  = (const float*)d_in[0];
    const float* Wg = (const float*)d_in[1];
    float* out = (float*)d_out;

    static int configured = 0;
    if (!configured) {
        cudaFuncSetAttribute(conv_unshuffle_mma,
                             cudaFuncAttributeMaxDynamicSharedMemorySize, SMEM_BYTES);
        configured = 1;
    }

    dim3 grid(WW / 128, HH, 8);   // (2, 256, 8) = 4096 CTAs
    conv_unshuffle_mma<<<grid, 256, SMEM_BYTES>>>(x, Wg, out);
}

// round 8
// speedup vs baseline: 2.4675x; 2.4584x over previous
#include <cuda_runtime.h>
#include <cuda_bf16.h>
#include <cstdint>

// Conv3x3(s1,p1) + PixelUnshuffle(2), warp-level mma.sync implicit GEMM, v2.
// x:(8,96,256,256)f32  W:(48,96,3,3)f32  out:(8,192,128,128)f32
// CTA: 32h x 32w output tile = 4 subtiles of 8h x 32w (M=256), all 48 oc.
// K = 96 ic x 9 taps; fp32 = bf16_hi + bf16_lo, 3 passes (hh,hl,lh), fp32 acc.
// Weights staged once per CTA (coalesced LDG), rows padded to 104 hw (no bank
// conflicts). A staged per 16-ic chunk with halo (10x34), LDGs for chunk c+1
// issued before MMA of chunk c (overlap).

#define IC  96
#define HH  256
#define WW  256
#define OCN 48

#define A_CELLS 340            // 10 x 34
#define A_STR   24             // halfwords per cell (16 ic + 8 pad) = 48 B
#define A_HALF  16320          // 340*24*2 bytes (hi plane)
#define W_STR   104            // halfwords per oc row (96 ic + 8 pad) = 208 B
#define W_HALF  89856          // 9*48*104*2 bytes
#define OFF_W   (2 * A_HALF)   // 32640
#define SMEM_BYTES (OFF_W + 2 * W_HALF)   // 212352

#define NSLOT 22               // ceil(340*16 / 256)

static __device__ __forceinline__ uint32_t smem_u32(const void* p) {
    uint32_t a;
    asm("{ .reg .u64 t; cvta.to.shared.u64 t, %1; cvt.u32.u64 %0, t; }" : "=r"(a) : "l"(p));
    return a;
}
static __device__ __forceinline__ void mma_bf16(float* d, const uint32_t* a, const uint32_t* b) {
    asm volatile(
        "mma.sync.aligned.m16n8k16.row.col.f32.bf16.bf16.f32 "
        "{%0,%1,%2,%3}, {%4,%5,%6,%7}, {%8,%9}, {%0,%1,%2,%3};"
        : "+f"(d[0]), "+f"(d[1]), "+f"(d[2]), "+f"(d[3])
        : "r"(a[0]), "r"(a[1]), "r"(a[2]), "r"(a[3]), "r"(b[0]), "r"(b[1]));
}
static __device__ __forceinline__ void ldsm_x4(uint32_t* r, uint32_t addr) {
    asm volatile("ldmatrix.sync.aligned.m8n8.x4.shared.b16 {%0,%1,%2,%3}, [%4];"
                 : "=r"(r[0]), "=r"(r[1]), "=r"(r[2]), "=r"(r[3]) : "r"(addr));
}
static __device__ __forceinline__ void ldsm_x2(uint32_t* r, uint32_t addr) {
    asm volatile("ldmatrix.sync.aligned.m8n8.x2.shared.b16 {%0,%1}, [%2];"
                 : "=r"(r[0]), "=r"(r[1]) : "r"(addr));
}
static __device__ __forceinline__ void split_bf16(float v, unsigned short& h, unsigned short& l) {
    __nv_bfloat16 hb = __float2bfloat16(v);
    __nv_bfloat16 lb = __float2bfloat16(v - __bfloat162float(hb));
    h = __bfloat16_as_ushort(hb);
    l = __bfloat16_as_ushort(lb);
}

__global__ void __launch_bounds__(256, 1)
conv_unshuffle_mma2(const float* __restrict__ x,
                    const float* __restrict__ Wg,
                    float* __restrict__ out)
{
    extern __shared__ __align__(128) char sm[];
    const uint32_t smb = smem_u32(sm);
    unsigned short* wHi = (unsigned short*)(sm + OFF_W);
    unsigned short* wLo = (unsigned short*)(sm + OFF_W + W_HALF);

    const int tid  = threadIdx.x;
    const int lane = tid & 31;
    const int wid  = tid >> 5;
    const int mbase = (wid & 3) * 64;
    const int nbase = (wid >> 2) * 24;

    const int w0  = blockIdx.x * 32;
    const int h0c = blockIdx.y * 32;
    const int b   = blockIdx.z;
    const long long x_b = (long long)b * IC * HH * WW;

    // ---- per-thread A-staging slot metadata (constant across chunks) ----
    int gOff[NSLOT];       // ic*65536 + hr*256 + win
    int pk[NSLOT];         // hr | (validW<<8) | (slotValid<<9)
    uint32_t sAddr[NSLOT]; // byte offset into A hi plane
#pragma unroll
    for (int j = 0; j < NSLOT; ++j) {
        const int idx = tid + j * 256;
        const int sv  = (idx < A_CELLS * 16) ? 1 : 0;
        const int id2 = sv ? idx : 0;
        const int ic  = id2 / A_CELLS;
        const int cel = id2 - ic * A_CELLS;
        const int hr  = cel / 34;
        const int wc  = cel - hr * 34;
        const int win = w0 + wc - 1;
        const int vw  = ((unsigned)win < WW) ? 1 : 0;
        gOff[j]  = ic * (HH * WW) + hr * WW + win;
        pk[j]    = hr | (vw << 8) | (sv << 9);
        sAddr[j] = (uint32_t)(cel * (A_STR * 2) + ic * 2);
    }

    // ---- per-lane ldmatrix bases ----
    const int lrow  = lane & 15;
    const int lkoff = (lane >> 4) * 16;
    uint32_t aB[4];
#pragma unroll
    for (int mt = 0; mt < 4; ++mt) {
        const int m  = mbase + mt * 16 + lrow;
        const int hl = m >> 5;
        const int wl = m & 31;
        aB[mt] = smb + (uint32_t)((hl * 34 + wl) * (A_STR * 2)) + lkoff;
    }
    const uint32_t bB  = smb + OFF_W + (uint32_t)((nbase + lrow) * (W_STR * 2)) + lkoff;
    const uint32_t bB2 = smb + OFF_W + (uint32_t)((nbase + 16 + (lane & 7)) * (W_STR * 2))
                       + ((lane >> 3) & 1) * 16;

    float v[NSLOT];
    auto LOADA = [&](int h0s, int ic0) {
        const long long base = x_b + (long long)ic0 * (HH * WW) + (long long)(h0s - 1) * WW;
#pragma unroll
        for (int j = 0; j < NSLOT; ++j) {
            const int hin = h0s - 1 + (pk[j] & 255);
            const bool ok = (pk[j] & 512) && (pk[j] & 256) && ((unsigned)hin < HH);
            v[j] = ok ? __ldg(&x[base + gOff[j]]) : 0.0f;
        }
    };

    // prefetch A(subtile 0, chunk 0); LDGs fly during weight staging
    LOADA(h0c, 0);

    // ---- stage ALL weights once, coalesced LDG, scatter STS ----
    for (int idx = tid; idx < OCN * IC * 9; idx += 256) {
        const int oc  = idx / (IC * 9);
        const int r   = idx - oc * (IC * 9);
        const int ic  = r / 9;
        const int tap = r - ic * 9;
        unsigned short hi, lo;
        split_bf16(Wg[idx], hi, lo);
        const int ha = (tap * OCN + oc) * W_STR + ic;
        wHi[ha] = hi;
        wLo[ha] = lo;
    }

    for (int st = 0; st < 4; ++st) {
        const int h0s = h0c + st * 8;
        float acc[4][3][4];
#pragma unroll
        for (int mt = 0; mt < 4; ++mt)
#pragma unroll
            for (int nt = 0; nt < 3; ++nt)
#pragma unroll
                for (int e = 0; e < 4; ++e) acc[mt][nt][e] = 0.0f;

#pragma unroll 1
        for (int ch = 0; ch < 6; ++ch) {
            __syncthreads();   // prior chunk's MMA reads done (or W staging done)
            // split + store this chunk's A values
#pragma unroll
            for (int j = 0; j < NSLOT; ++j) {
                if (pk[j] & 512) {
                    unsigned short hi, lo;
                    split_bf16(v[j], hi, lo);
                    *(unsigned short*)(sm + sAddr[j])          = hi;
                    *(unsigned short*)(sm + A_HALF + sAddr[j]) = lo;
                }
            }
            __syncthreads();   // staging visible to all warps

            // issue next chunk's LDGs (in flight during MMA below)
            if (!(st == 3 && ch == 5)) {
                const int nst = (ch < 5) ? st : st + 1;
                const int nch = (ch < 5) ? ch + 1 : 0;
                LOADA(h0c + nst * 8, nch * 16);
            }

            // ---- MMA over 9 taps ----
            const uint32_t icb = (uint32_t)(ch * 32);   // 16 ic * 2 B
#pragma unroll
            for (int tap = 0; tap < 9; ++tap) {
                const int dy = tap / 3;
                const int dx = tap - dy * 3;
                const uint32_t aoff = (uint32_t)((dy * 34 + dx) * (A_STR * 2));
                const uint32_t woff = (uint32_t)(tap * (OCN * W_STR * 2)) + icb;

                uint32_t ah[4][4], al[4][4];
#pragma unroll
                for (int mt = 0; mt < 4; ++mt) {
                    ldsm_x4(ah[mt], aB[mt] + aoff);
                    ldsm_x4(al[mt], aB[mt] + aoff + A_HALF);
                }
                uint32_t bh01[4], bh2[2], bl01[4], bl2[2];
                ldsm_x4(bh01, bB  + woff);
                ldsm_x2(bh2,  bB2 + woff);
                ldsm_x4(bl01, bB  + woff + W_HALF);
                ldsm_x2(bl2,  bB2 + woff + W_HALF);

                uint32_t bh[3][2] = { {bh01[0], bh01[2]}, {bh01[1], bh01[3]}, {bh2[0], bh2[1]} };
                uint32_t bl[3][2] = { {bl01[0], bl01[2]}, {bl01[1], bl01[3]}, {bl2[0], bl2[1]} };

#pragma unroll
                for (int mt = 0; mt < 4; ++mt)
#pragma unroll
                    for (int nt = 0; nt < 3; ++nt) {
                        mma_bf16(acc[mt][nt], ah[mt], bh[nt]);
                        mma_bf16(acc[mt][nt], ah[mt], bl[nt]);
                        mma_bf16(acc[mt][nt], al[mt], bh[nt]);
                    }
            }
        }

        // ---- epilogue: fused PixelUnshuffle(2) scatter for this subtile ----
        const int r0 = lane >> 2;
        const int c0 = (lane & 3) * 2;
#pragma unroll
        for (int mt = 0; mt < 4; ++mt) {
#pragma unroll
            for (int pair = 0; pair < 2; ++pair) {
                const int m  = mbase + mt * 16 + r0 + pair * 8;
                const int hl = m >> 5;
                const int wl = m & 31;
                const int h  = h0s + hl;
                const int w  = w0 + wl;
                const int cb = (h & 1) * 2 + (w & 1);
                const long long pxbase =
                    (((long long)b * 192 + cb) * 128 + (h >> 1)) * 128 + (w >> 1);
#pragma unroll
                for (int nt = 0; nt < 3; ++nt) {
                    const int oc0 = nbase + nt * 8 + c0;
                    out[pxbase + (long long)(oc0    ) * 4 * 128 * 128] = acc[mt][nt][pair * 2 + 0];
                    out[pxbase + (long long)(oc0 + 1) * 4 * 128 * 128] = acc[mt][nt][pair * 2 + 1];
                }
            }
        }
    }
}

extern "C" void kernel_launch(void* const* d_in, const int* in_sizes, int n_in,
                              void* d_out, int out_size)
{
    const float* x  = (const float*)d_in[0];
    const float* Wg = (const float*)d_in[1];
    float* out = (float*)d_out;

    static int configured = 0;
    if (!configured) {
        cudaFuncSetAttribute(conv_unshuffle_mma2,
                             cudaFuncAttributeMaxDynamicSharedMemorySize, SMEM_BYTES);
        configured = 1;
    }

    dim3 grid(WW / 32, HH / 32, 8);   // (8, 8, 8) = 512 CTAs
    conv_unshuffle_mma2<<<grid, 256, SMEM_BYTES>>>(x, Wg, out);
}

// round 12
// speedup vs baseline: 2.5679x; 1.0407x over previous
#include <cuda_runtime.h>
#include <cuda_bf16.h>
#include <cstdint>

// Conv3x3(s1,p1) + PixelUnshuffle(2), warp-level mma.sync implicit GEMM, v3.
// x:(8,96,256,256)f32  W:(48,96,3,3)f32  out:(8,192,128,128)f32
// CTA: 32h x 32w tile = 4 subtiles of 8h x 32w (M=256), all 48 oc. 512 threads,
// 16 warps = 8 m-groups x 2 n-groups. K = 96 ic x 9 taps; fp32 = bf16_hi+bf16_lo,
// 3 passes (hh,hl,lh) ordered pass-major (no RAW chains), fp32 accum.
// Weights staged once per CTA (coalesced), A per 16-ic chunk with halo (10x34),
// next chunk's LDGs issued before this chunk's MMAs.

#define IC  96
#define HH  256
#define WW  256
#define OCN 48

#define A_CELLS 340            // 10 x 34
#define A_STR   24             // halfwords per cell (16 ic + 8 pad) = 48 B
#define A_HALF  16320          // 340*24*2 bytes (hi plane)
#define W_STR   104            // halfwords per oc row (96 ic + 8 pad) = 208 B
#define W_HALF  89856          // 9*48*104*2 bytes
#define OFF_W   (2 * A_HALF)   // 32640
#define SMEM_BYTES (OFF_W + 2 * W_HALF)   // 212352

#define NTHREADS 512
#define NSLOT 11               // ceil(340*16 / 512)

static __device__ __forceinline__ uint32_t smem_u32(const void* p) {
    uint32_t a;
    asm("{ .reg .u64 t; cvta.to.shared.u64 t, %1; cvt.u32.u64 %0, t; }" : "=r"(a) : "l"(p));
    return a;
}
static __device__ __forceinline__ void mma_bf16(float* d, const uint32_t* a, const uint32_t* b) {
    asm volatile(
        "mma.sync.aligned.m16n8k16.row.col.f32.bf16.bf16.f32 "
        "{%0,%1,%2,%3}, {%4,%5,%6,%7}, {%8,%9}, {%0,%1,%2,%3};"
        : "+f"(d[0]), "+f"(d[1]), "+f"(d[2]), "+f"(d[3])
        : "r"(a[0]), "r"(a[1]), "r"(a[2]), "r"(a[3]), "r"(b[0]), "r"(b[1]));
}
static __device__ __forceinline__ void ldsm_x4(uint32_t* r, uint32_t addr) {
    asm volatile("ldmatrix.sync.aligned.m8n8.x4.shared.b16 {%0,%1,%2,%3}, [%4];"
                 : "=r"(r[0]), "=r"(r[1]), "=r"(r[2]), "=r"(r[3]) : "r"(addr));
}
static __device__ __forceinline__ void ldsm_x2(uint32_t* r, uint32_t addr) {
    asm volatile("ldmatrix.sync.aligned.m8n8.x2.shared.b16 {%0,%1}, [%2];"
                 : "=r"(r[0]), "=r"(r[1]) : "r"(addr));
}
static __device__ __forceinline__ void split_bf16(float v, unsigned short& h, unsigned short& l) {
    __nv_bfloat16 hb = __float2bfloat16(v);
    __nv_bfloat16 lb = __float2bfloat16(v - __bfloat162float(hb));
    h = __bfloat16_as_ushort(hb);
    l = __bfloat16_as_ushort(lb);
}

__global__ void __launch_bounds__(NTHREADS, 1)
conv_unshuffle_mma3(const float* __restrict__ x,
                    const float* __restrict__ Wg,
                    float* __restrict__ out)
{
    extern __shared__ __align__(128) char sm[];
    const uint32_t smb = smem_u32(sm);
    unsigned short* wHi = (unsigned short*)(sm + OFF_W);
    unsigned short* wLo = (unsigned short*)(sm + OFF_W + W_HALF);

    const int tid  = threadIdx.x;
    const int lane = tid & 31;
    const int wid  = tid >> 5;
    const int mbase = (wid & 7) * 32;       // 8 m-groups of 32 rows
    const int nbase = (wid >> 3) * 24;      // 2 n-groups of 24 oc

    const int w0  = blockIdx.x * 32;
    const int h0c = blockIdx.y * 32;
    const int b   = blockIdx.z;
    const long long x_b = (long long)b * IC * HH * WW;

    // ---- per-thread A-staging slot metadata (constant across chunks) ----
    int gOff[NSLOT];       // ic*65536 + hr*256 + win
    int pk[NSLOT];         // hr | (validW<<8) | (slotValid<<9)
    uint32_t sAddr[NSLOT]; // byte offset into A hi plane
#pragma unroll
    for (int j = 0; j < NSLOT; ++j) {
        const int idx = tid + j * NTHREADS;
        const int sv  = (idx < A_CELLS * 16) ? 1 : 0;
        const int id2 = sv ? idx : 0;
        const int ic  = id2 / A_CELLS;
        const int cel = id2 - ic * A_CELLS;
        const int hr  = cel / 34;
        const int wc  = cel - hr * 34;
        const int win = w0 + wc - 1;
        const int vw  = ((unsigned)win < WW) ? 1 : 0;
        gOff[j]  = ic * (HH * WW) + hr * WW + win;
        pk[j]    = hr | (vw << 8) | (sv << 9);
        sAddr[j] = (uint32_t)(cel * (A_STR * 2) + ic * 2);
    }

    // ---- per-lane ldmatrix bases ----
    const int lrow  = lane & 15;
    const int lkoff = (lane >> 4) * 16;
    uint32_t aB[2];
#pragma unroll
    for (int mt = 0; mt < 2; ++mt) {
        const int m  = mbase + mt * 16 + lrow;
        const int hl = m >> 5;
        const int wl = m & 31;
        aB[mt] = smb + (uint32_t)((hl * 34 + wl) * (A_STR * 2)) + lkoff;
    }
    const uint32_t bB  = smb + OFF_W + (uint32_t)((nbase + lrow) * (W_STR * 2)) + lkoff;
    const uint32_t bB2 = smb + OFF_W + (uint32_t)((nbase + 16 + (lane & 7)) * (W_STR * 2))
                       + ((lane >> 3) & 1) * 16;

    float v[NSLOT];
    auto LOADA = [&](int h0s, int ic0) {
        const long long base = x_b + (long long)ic0 * (HH * WW) + (long long)(h0s - 1) * WW;
#pragma unroll
        for (int j = 0; j < NSLOT; ++j) {
            const int hin = h0s - 1 + (pk[j] & 255);
            const bool ok = (pk[j] & 512) && (pk[j] & 256) && ((unsigned)hin < HH);
            v[j] = ok ? __ldg(&x[base + gOff[j]]) : 0.0f;
        }
    };

    // prefetch A(subtile 0, chunk 0); LDGs fly during weight staging
    LOADA(h0c, 0);

    // ---- stage ALL weights once, coalesced LDG, scatter STS ----
    for (int idx = tid; idx < OCN * IC * 9; idx += NTHREADS) {
        const int oc  = idx / (IC * 9);
        const int r   = idx - oc * (IC * 9);
        const int ic  = r / 9;
        const int tap = r - ic * 9;
        unsigned short hi, lo;
        split_bf16(Wg[idx], hi, lo);
        const int ha = (tap * OCN + oc) * W_STR + ic;
        wHi[ha] = hi;
        wLo[ha] = lo;
    }

    for (int st = 0; st < 4; ++st) {
        const int h0s = h0c + st * 8;
        float acc[2][3][4];
#pragma unroll
        for (int mt = 0; mt < 2; ++mt)
#pragma unroll
            for (int nt = 0; nt < 3; ++nt)
#pragma unroll
                for (int e = 0; e < 4; ++e) acc[mt][nt][e] = 0.0f;

#pragma unroll 1
        for (int ch = 0; ch < 6; ++ch) {
            __syncthreads();   // prior chunk's MMA reads done (or W staging done)
            // split + store this chunk's A values
#pragma unroll
            for (int j = 0; j < NSLOT; ++j) {
                if (pk[j] & 512) {
                    unsigned short hi, lo;
                    split_bf16(v[j], hi, lo);
                    *(unsigned short*)(sm + sAddr[j])          = hi;
                    *(unsigned short*)(sm + A_HALF + sAddr[j]) = lo;
                }
            }
            __syncthreads();   // staging visible to all warps

            // issue next chunk's LDGs (in flight during MMA below)
            if (!(st == 3 && ch == 5)) {
                const int nst = (ch < 5) ? st : st + 1;
                const int nch = (ch < 5) ? ch + 1 : 0;
                LOADA(h0c + nst * 8, nch * 16);
            }

            // ---- MMA over 9 taps, pass-major (no back-to-back acc reuse) ----
            const uint32_t icb = (uint32_t)(ch * 32);   // 16 ic * 2 B
#pragma unroll
            for (int tap = 0; tap < 9; ++tap) {
                const int dy = tap / 3;
                const int dx = tap - dy * 3;
                const uint32_t aoff = (uint32_t)((dy * 34 + dx) * (A_STR * 2));
                const uint32_t woff = (uint32_t)(tap * (OCN * W_STR * 2)) + icb;

                uint32_t ah[2][4], al[2][4];
#pragma unroll
                for (int mt = 0; mt < 2; ++mt) {
                    ldsm_x4(ah[mt], aB[mt] + aoff);
                    ldsm_x4(al[mt], aB[mt] + aoff + A_HALF);
                }
                uint32_t bh01[4], bh2[2], bl01[4], bl2[2];
                ldsm_x4(bh01, bB  + woff);
                ldsm_x2(bh2,  bB2 + woff);
                ldsm_x4(bl01, bB  + woff + W_HALF);
                ldsm_x2(bl2,  bB2 + woff + W_HALF);

                uint32_t bh[3][2] = { {bh01[0], bh01[2]}, {bh01[1], bh01[3]}, {bh2[0], bh2[1]} };
                uint32_t bl[3][2] = { {bl01[0], bl01[2]}, {bl01[1], bl01[3]}, {bl2[0], bl2[1]} };

                // pass 1: ah * bh
#pragma unroll
                for (int mt = 0; mt < 2; ++mt)
#pragma unroll
                    for (int nt = 0; nt < 3; ++nt)
                        mma_bf16(acc[mt][nt], ah[mt], bh[nt]);
                // pass 2: ah * bl
#pragma unroll
                for (int mt = 0; mt < 2; ++mt)
#pragma unroll
                    for (int nt = 0; nt < 3; ++nt)
                        mma_bf16(acc[mt][nt], ah[mt], bl[nt]);
                // pass 3: al * bh
#pragma unroll
                for (int mt = 0; mt < 2; ++mt)
#pragma unroll
                    for (int nt = 0; nt < 3; ++nt)
                        mma_bf16(acc[mt][nt], al[mt], bh[nt]);
            }
        }

        // ---- epilogue: fused PixelUnshuffle(2) scatter for this subtile ----
        const int r0 = lane >> 2;
        const int c0 = (lane & 3) * 2;
#pragma unroll
        for (int mt = 0; mt < 2; ++mt) {
#pragma unroll
            for (int pair = 0; pair < 2; ++pair) {
                const int m  = mbase + mt * 16 + r0 + pair * 8;
                const int hl = m >> 5;
                const int wl = m & 31;
                const int h  = h0s + hl;
                const int w  = w0 + wl;
                const int cb = (h & 1) * 2 + (w & 1);
                const long long pxbase =
                    (((long long)b * 192 + cb) * 128 + (h >> 1)) * 128 + (w >> 1);
#pragma unroll
                for (int nt = 0; nt < 3; ++nt) {
                    const int oc0 = nbase + nt * 8 + c0;
                    out[pxbase + (long long)(oc0    ) * 4 * 128 * 128] = acc[mt][nt][pair * 2 + 0];
                    out[pxbase + (long long)(oc0 + 1) * 4 * 128 * 128] = acc[mt][nt][pair * 2 + 1];
                }
            }
        }
    }
}

extern "C" void kernel_launch(void* const* d_in, const int* in_sizes, int n_in,
                              void* d_out, int out_size)
{
    const float* x  = (const float*)d_in[0];
    const float* Wg = (const float*)d_in[1];
    float* out = (float*)d_out;

    static int configured = 0;
    if (!configured) {
        cudaFuncSetAttribute(conv_unshuffle_mma3,
                             cudaFuncAttributeMaxDynamicSharedMemorySize, SMEM_BYTES);
        configured = 1;
    }

    dim3 grid(WW / 32, HH / 32, 8);   // (8, 8, 8) = 512 CTAs
    conv_unshuffle_mma3<<<grid, NTHREADS, SMEM_BYTES>>>(x, Wg, out);
}